// round 13
// baseline (speedup 1.0000x reference)
#include <cuda_runtime.h>
#include <cuda_bf16.h>

#define BB 128   // batch
#define NN 50    // entities per doc
#define KK 20    // neighbors
#define DD 128   // embedding dim
#define NK (NN*KK)          // 1000
#define BN (BB*NN)          // 6400
#define TOT (BB*NN*KK)      // 128000

typedef unsigned long long ull;

// scratch
__device__ float g_exp[TOT];          // transposed: exp(logit)[nk][b]
__device__ float g_den[1024];         // softmax denominators per (n,k)
__device__ float g_rel_dot[128];      // R=100, padded

// ---- packed f32x2 helpers (sm_103a) --------------------------------------
__device__ __forceinline__ ull pack2(float lo, float hi) {
    ull r;
    asm("mov.b64 %0, {%1, %2};" : "=l"(r) : "f"(lo), "f"(hi));
    return r;
}
__device__ __forceinline__ void unpack2(ull v, float& lo, float& hi) {
    asm("mov.b64 {%0, %1}, %2;" : "=f"(lo), "=f"(hi) : "l"(v));
}
__device__ __forceinline__ ull fma2(ull a, ull b, ull c) {
    ull d;
    asm("fma.rn.f32x2 %0, %1, %2, %3;" : "=l"(d) : "l"(a), "l"(b), "l"(c));
    return d;
}

// ---------------------------------------------------------------------------
// K0 (tiny): zero g_den; rel_dot[r] = dot(rel_emb[r], w2). 25 blocks x 128.
// ---------------------------------------------------------------------------
__global__ __launch_bounds__(128) void k_pre(
    const float* __restrict__ rel_emb,
    const float* __restrict__ W_att)
{
    int gtid = blockIdx.x * 128 + threadIdx.x;
    if (gtid < 1024) g_den[gtid] = 0.0f;

    int warp = gtid >> 5;
    int lane = threadIdx.x & 31;
    if (warp >= 100) return;

    float4 a  = ((const float4*)(rel_emb + (size_t)warp * DD))[lane];
    float4 wv = ((const float4*)(W_att + 2 * DD))[lane];
    float s = a.x*wv.x + a.y*wv.y + a.z*wv.z + a.w*wv.w;
    #pragma unroll
    for (int off = 16; off > 0; off >>= 1)
        s += __shfl_xor_sync(0xffffffffu, s, off);
    if (lane == 0) g_rel_dot[warp] = s;
}

// ---------------------------------------------------------------------------
// K1: one warp per (bn, k-quad). 4 neighbor rows + the (L1-hot) ee row in
// flight; 5 interleaved butterfly chains (s0..s3, se). Lanes 0-3 each finish
// one k: exp(relu(logit)) + atomicAdd into the softmax denominator.
// ---------------------------------------------------------------------------
__global__ __launch_bounds__(256) void k_logits(
    const int* __restrict__ entity_ids,
    const int* __restrict__ adj_entity,
    const int* __restrict__ adj_relation,
    const float* __restrict__ ent_emb,
    const float* __restrict__ W_att,
    const float* __restrict__ b_att)
{
    int warp = (blockIdx.x * blockDim.x + threadIdx.x) >> 5;  // 0..TOT/4-1
    int lane = threadIdx.x & 31;

    int bn = warp / 5;
    int k0 = (warp - bn * 5) * 4;     // 0,4,8,12,16
    int b  = bn / NN;
    int n  = bn - b * NN;

    int eid = entity_ids[bn];
    int4 nid = *(const int4*)(adj_entity   + eid * KK + k0);  // 16B-aligned
    int4 rid = *(const int4*)(adj_relation + eid * KK + k0);

    float4 w0 = ((const float4*)(W_att))[lane];
    float4 w1 = ((const float4*)(W_att + DD))[lane];

    float4 ee = ((const float4*)(ent_emb + (size_t)eid   * DD))[lane];
    float4 v0 = ((const float4*)(ent_emb + (size_t)nid.x * DD))[lane];
    float4 v1 = ((const float4*)(ent_emb + (size_t)nid.y * DD))[lane];
    float4 v2 = ((const float4*)(ent_emb + (size_t)nid.z * DD))[lane];
    float4 v3 = ((const float4*)(ent_emb + (size_t)nid.w * DD))[lane];

    float se = ee.x*w0.x + ee.y*w0.y + ee.z*w0.z + ee.w*w0.w;
    float s0 = v0.x*w1.x + v0.y*w1.y + v0.z*w1.z + v0.w*w1.w;
    float s1 = v1.x*w1.x + v1.y*w1.y + v1.z*w1.z + v1.w*w1.w;
    float s2 = v2.x*w1.x + v2.y*w1.y + v2.z*w1.z + v2.w*w1.w;
    float s3 = v3.x*w1.x + v3.y*w1.y + v3.z*w1.z + v3.w*w1.w;

    #pragma unroll
    for (int off = 16; off > 0; off >>= 1) {
        se += __shfl_xor_sync(0xffffffffu, se, off);
        s0 += __shfl_xor_sync(0xffffffffu, s0, off);
        s1 += __shfl_xor_sync(0xffffffffu, s1, off);
        s2 += __shfl_xor_sync(0xffffffffu, s2, off);
        s3 += __shfl_xor_sync(0xffffffffu, s3, off);
    }

    if (lane < 4) {
        float s  = (lane == 0) ? s0 : (lane == 1) ? s1 : (lane == 2) ? s2 : s3;
        int   rv = (lane == 0) ? rid.x : (lane == 1) ? rid.y
                 : (lane == 2) ? rid.z : rid.w;
        float base = se + b_att[0];
        float e = __expf(fmaxf(s + base + g_rel_dot[rv], 0.0f));
        int nk = n * KK + k0 + lane;
        g_exp[nk * BB + b] = e;
        atomicAdd(&g_den[nk], e);
    }
}

// ---------------------------------------------------------------------------
// K2: fused gather + gemm. One block per 16 (b,n) rows, 128 threads, grid 400.
// Phase A: stage ids + normalized att (dup-packed).
// Phase B: thread = (d-pair, half -> 8 rows); 20 LDG.64 in flight per row;
//          writes transposed tile sT[j][row].
// Phase C: round-7 gemm loop, W register-prefetched 8 deep, 8 FFMA2/j.
// ---------------------------------------------------------------------------
#define GROWS  16
#define GPITCH 20     // floats per j-row: 80B (16B-aligned)

__global__ __launch_bounds__(128) void k_gg(
    const int* __restrict__ entity_ids,
    const int* __restrict__ adj_entity,
    const float* __restrict__ ent_emb,
    const float* __restrict__ W_conv,
    const float* __restrict__ b_conv,
    float* __restrict__ out)
{
    __shared__ float sT[2 * DD * GPITCH];   // [256][20] = 20 KB
    __shared__ int   s_eid[GROWS];
    __shared__ int   s_nid[GROWS * KK];     // 320
    __shared__ ull   s_att2[GROWS * KK];    // 320 dup'd att pairs

    int t   = threadIdx.x;
    int bn0 = blockIdx.x * GROWS;

    // ---- Phase A ----
    if (t < GROWS) s_eid[t] = entity_ids[bn0 + t];
    for (int i = t; i < GROWS * KK; i += 128) {
        int rl = i / KK;
        int k  = i - rl * KK;
        int bn = bn0 + rl;
        int b  = bn / NN;
        int n  = bn - b * NN;
        int eid = entity_ids[bn];
        s_nid[i] = adj_entity[eid * KK + k];
        int nk = n * KK + k;
        float a = __fdividef(g_exp[nk * BB + b], g_den[nk]);
        s_att2[i] = pack2(a, a);
    }
    __syncthreads();

    int p    = t & 63;      // d-pair index: d0 = 2p
    int half = t >> 6;      // 0/1 -> rows half*8 .. half*8+7
    int d0   = 2 * p;

    // ---- Phase B ----
    #pragma unroll 1
    for (int m = 0; m < 8; m++) {
        int r  = half * 8 + m;
        int eid = s_eid[r];

        ull ee2 = *(const ull*)(ent_emb + (size_t)eid * DD + d0);

        ull v[KK];
        #pragma unroll
        for (int k = 0; k < KK; k++)
            v[k] = *(const ull*)(ent_emb + (size_t)s_nid[r * KK + k] * DD + d0);

        ull acc = 0ull;
        #pragma unroll
        for (int k = 0; k < KK; k++)
            acc = fma2(s_att2[r * KK + k], v[k], acc);

        float elo, ehi, nlo, nhi;
        unpack2(ee2, elo, ehi);
        unpack2(acc, nlo, nhi);
        sT[(d0 + 0) * GPITCH + r]      = elo;
        sT[(d0 + 1) * GPITCH + r]      = ehi;
        sT[(DD + d0 + 0) * GPITCH + r] = nlo;
        sT[(DD + d0 + 1) * GPITCH + r] = nhi;
    }
    __syncthreads();

    // ---- Phase C ----
    int rg = half;

    ull acc[2][4];
    {
        ull i0 = pack2(b_conv[d0],     b_conv[d0]);
        ull i1 = pack2(b_conv[d0 + 1], b_conv[d0 + 1]);
        #pragma unroll
        for (int rp = 0; rp < 4; rp++) { acc[0][rp] = i0; acc[1][rp] = i1; }
    }

    const float* Wp = W_conv + d0;
    const float* sb = sT + rg * 8;

    float2 wb[8];
    #pragma unroll
    for (int i = 0; i < 8; i++)
        wb[i] = *(const float2*)(Wp + i * DD);

    #pragma unroll 1
    for (int jt = 0; jt < 2 * DD; jt += 8) {
        float2 wc[8];
        #pragma unroll
        for (int i = 0; i < 8; i++) wc[i] = wb[i];

        int jn = (jt + 8) & (2 * DD - 1);
        #pragma unroll
        for (int i = 0; i < 8; i++)
            wb[i] = *(const float2*)(Wp + (jn + i) * DD);

        #pragma unroll
        for (int i = 0; i < 8; i++) {
            int j = jt + i;
            ull w0 = pack2(wc[i].x, wc[i].x);
            ull w1 = pack2(wc[i].y, wc[i].y);
            ulonglong2 pa = *(const ulonglong2*)(sb + j * GPITCH);       // rows 0-3
            ulonglong2 pb = *(const ulonglong2*)(sb + j * GPITCH + 4);   // rows 4-7
            acc[0][0] = fma2(pa.x, w0, acc[0][0]);
            acc[1][0] = fma2(pa.x, w1, acc[1][0]);
            acc[0][1] = fma2(pa.y, w0, acc[0][1]);
            acc[1][1] = fma2(pa.y, w1, acc[1][1]);
            acc[0][2] = fma2(pb.x, w0, acc[0][2]);
            acc[1][2] = fma2(pb.x, w1, acc[1][2]);
            acc[0][3] = fma2(pb.y, w0, acc[0][3]);
            acc[1][3] = fma2(pb.y, w1, acc[1][3]);
        }
    }

    #pragma unroll
    for (int rp = 0; rp < 4; rp++) {
        float lo0, hi0, lo1, hi1;
        unpack2(acc[0][rp], lo0, hi0);
        unpack2(acc[1][rp], lo1, hi1);
        int r0 = bn0 + rg * 8 + rp * 2;
        float2 o0 = make_float2(fmaxf(lo0, 0.0f), fmaxf(lo1, 0.0f));
        float2 o1 = make_float2(fmaxf(hi0, 0.0f), fmaxf(hi1, 0.0f));
        *(float2*)(out + (size_t)r0 * DD + d0)       = o0;
        *(float2*)(out + (size_t)(r0 + 1) * DD + d0) = o1;
    }
}

// ---------------------------------------------------------------------------
extern "C" void kernel_launch(void* const* d_in, const int* in_sizes, int n_in,
                              void* d_out, int out_size)
{
    const int*   entity_ids = (const int*)  d_in[0];
    const int*   adj_entity = (const int*)  d_in[1];
    const int*   adj_rel    = (const int*)  d_in[2];
    const float* ent_emb    = (const float*)d_in[3];
    const float* rel_emb    = (const float*)d_in[4];
    const float* W_att      = (const float*)d_in[5];
    const float* b_att      = (const float*)d_in[6];
    const float* W_conv     = (const float*)d_in[7];
    const float* b_conv     = (const float*)d_in[8];
    float* out = (float*)d_out;

    k_pre<<<25, 128>>>(rel_emb, W_att);

    k_logits<<<TOT / 4 / 8, 256>>>(entity_ids, adj_entity, adj_rel,
                                   ent_emb, W_att, b_att);

    k_gg<<<BN / GROWS, 128>>>(entity_ids, adj_entity, ent_emb,
                              W_conv, b_conv, out);
}

// round 14
// speedup vs baseline: 1.0558x; 1.0558x over previous
#include <cuda_runtime.h>
#include <cuda_bf16.h>

#define BB 128   // batch
#define NN 50    // entities per doc
#define KK 20    // neighbors
#define DD 128   // embedding dim
#define NK (NN*KK)          // 1000
#define BN (BB*NN)          // 6400
#define TOT (BB*NN*KK)      // 128000

typedef unsigned long long ull;

// scratch
__device__ float g_exp[TOT];          // transposed: exp(logit)[nk][b]
__device__ float g_den[1024];         // softmax denominators per (n,k)
__device__ float g_ee_dot[BN];
__device__ float g_rel_dot[128];      // R=100, padded

// ---- packed f32x2 helpers (sm_103a) --------------------------------------
__device__ __forceinline__ ull pack2(float lo, float hi) {
    ull r;
    asm("mov.b64 %0, {%1, %2};" : "=l"(r) : "f"(lo), "f"(hi));
    return r;
}
__device__ __forceinline__ void unpack2(ull v, float& lo, float& hi) {
    asm("mov.b64 {%0, %1}, %2;" : "=f"(lo), "=f"(hi) : "l"(v));
}
__device__ __forceinline__ ull fma2(ull a, ull b, ull c) {
    ull d;
    asm("fma.rn.f32x2 %0, %1, %2, %3;" : "=l"(d) : "l"(a), "l"(b), "l"(c));
    return d;
}

// ---------------------------------------------------------------------------
// K0: zero g_den; ee_dot (2 rows/warp, 3200 warps) + rel_dot (2 rows/warp,
// 50 warps). Two independent load chains per warp (MLP=2 on the eid->row
// dependent chain).
// ---------------------------------------------------------------------------
#define PRE_W (BN / 2 + 50)   // 3250 warps

__global__ __launch_bounds__(256) void k_pre(
    const int* __restrict__ entity_ids,
    const float* __restrict__ ent_emb,
    const float* __restrict__ rel_emb,
    const float* __restrict__ W_att)
{
    int gtid = blockIdx.x * 256 + threadIdx.x;
    if (gtid < 1024) g_den[gtid] = 0.0f;

    int warp = gtid >> 5;
    int lane = threadIdx.x & 31;
    if (warp >= PRE_W) return;

    const float4 *rowA, *rowB, *w;
    if (warp < BN / 2) {
        int bn0 = warp * 2;
        int eA = entity_ids[bn0];
        int eB = entity_ids[bn0 + 1];
        rowA = (const float4*)(ent_emb + (size_t)eA * DD);
        rowB = (const float4*)(ent_emb + (size_t)eB * DD);
        w    = (const float4*)(W_att);            // w0
    } else {
        int r0 = (warp - BN / 2) * 2;
        rowA = (const float4*)(rel_emb + (size_t)r0 * DD);
        rowB = (const float4*)(rel_emb + (size_t)(r0 + 1) * DD);
        w    = (const float4*)(W_att + 2 * DD);   // w2
    }
    float4 a = rowA[lane];
    float4 b = rowB[lane];
    float4 wv = w[lane];
    float sa = a.x*wv.x + a.y*wv.y + a.z*wv.z + a.w*wv.w;
    float sb = b.x*wv.x + b.y*wv.y + b.z*wv.z + b.w*wv.w;
    #pragma unroll
    for (int off = 16; off > 0; off >>= 1) {
        sa += __shfl_xor_sync(0xffffffffu, sa, off);
        sb += __shfl_xor_sync(0xffffffffu, sb, off);
    }
    if (lane == 0) {
        if (warp < BN / 2) {
            g_ee_dot[warp * 2]     = sa;
            g_ee_dot[warp * 2 + 1] = sb;
        } else {
            int r0 = (warp - BN / 2) * 2;
            g_rel_dot[r0]     = sa;
            g_rel_dot[r0 + 1] = sb;
        }
    }
}

// ---------------------------------------------------------------------------
// K1: one warp per (bn, k-quad): 4 neighbor rows in flight,
// 4 interleaved butterflies; lanes 0-3 each finish one k (exp + atomic den).
// ---------------------------------------------------------------------------
__global__ __launch_bounds__(256) void k_logits(
    const int* __restrict__ entity_ids,
    const int* __restrict__ adj_entity,
    const int* __restrict__ adj_relation,
    const float* __restrict__ ent_emb,
    const float* __restrict__ W_att,
    const float* __restrict__ b_att)
{
    int warp = (blockIdx.x * blockDim.x + threadIdx.x) >> 5;  // 0..TOT/4-1
    int lane = threadIdx.x & 31;

    int bn = warp / 5;
    int k0 = (warp - bn * 5) * 4;     // 0,4,8,12,16
    int b  = bn / NN;
    int n  = bn - b * NN;

    int eid = entity_ids[bn];
    int4 nid = *(const int4*)(adj_entity   + eid * KK + k0);  // 16B-aligned
    int4 rid = *(const int4*)(adj_relation + eid * KK + k0);

    float4 wv = ((const float4*)(W_att + DD))[lane];

    float4 v0 = ((const float4*)(ent_emb + (size_t)nid.x * DD))[lane];
    float4 v1 = ((const float4*)(ent_emb + (size_t)nid.y * DD))[lane];
    float4 v2 = ((const float4*)(ent_emb + (size_t)nid.z * DD))[lane];
    float4 v3 = ((const float4*)(ent_emb + (size_t)nid.w * DD))[lane];

    float s0 = v0.x*wv.x + v0.y*wv.y + v0.z*wv.z + v0.w*wv.w;
    float s1 = v1.x*wv.x + v1.y*wv.y + v1.z*wv.z + v1.w*wv.w;
    float s2 = v2.x*wv.x + v2.y*wv.y + v2.z*wv.z + v2.w*wv.w;
    float s3 = v3.x*wv.x + v3.y*wv.y + v3.z*wv.z + v3.w*wv.w;

    #pragma unroll
    for (int off = 16; off > 0; off >>= 1) {
        s0 += __shfl_xor_sync(0xffffffffu, s0, off);
        s1 += __shfl_xor_sync(0xffffffffu, s1, off);
        s2 += __shfl_xor_sync(0xffffffffu, s2, off);
        s3 += __shfl_xor_sync(0xffffffffu, s3, off);
    }

    if (lane < 4) {
        float s  = (lane == 0) ? s0 : (lane == 1) ? s1 : (lane == 2) ? s2 : s3;
        int   rv = (lane == 0) ? rid.x : (lane == 1) ? rid.y
                 : (lane == 2) ? rid.z : rid.w;
        float base = g_ee_dot[bn] + b_att[0];
        float e = __expf(fmaxf(s + base + g_rel_dot[rv], 0.0f));
        int nk = n * KK + k0 + lane;
        g_exp[nk * BB + b] = e;
        atomicAdd(&g_den[nk], e);
    }
}

// ---------------------------------------------------------------------------
// K2: fused gather + gemm. One block per 16 (b,n) rows, 128 threads, grid 400.
// Phase A: stage ids + normalized att (dup-packed).
// Phase B: thread = (d-pair, half -> 8 rows), processed in interleaved PAIRS:
//          both rows' 20 LDG.64 issued before the FMA chains (2x MLP).
// Phase C: round-7 gemm loop, W register-prefetched 8 deep, 8 FFMA2/j.
// ---------------------------------------------------------------------------
#define GROWS  16
#define GPITCH 20     // floats per j-row: 80B (16B-aligned)

__global__ __launch_bounds__(128) void k_gg(
    const int* __restrict__ entity_ids,
    const int* __restrict__ adj_entity,
    const float* __restrict__ ent_emb,
    const float* __restrict__ W_conv,
    const float* __restrict__ b_conv,
    float* __restrict__ out)
{
    __shared__ float sT[2 * DD * GPITCH];   // [256][20] = 20 KB
    __shared__ int   s_eid[GROWS];
    __shared__ int   s_nid[GROWS * KK];     // 320
    __shared__ ull   s_att2[GROWS * KK];    // 320 dup'd att pairs

    int t   = threadIdx.x;
    int bn0 = blockIdx.x * GROWS;

    // ---- Phase A ----
    if (t < GROWS) s_eid[t] = entity_ids[bn0 + t];
    for (int i = t; i < GROWS * KK; i += 128) {
        int rl = i / KK;
        int k  = i - rl * KK;
        int bn = bn0 + rl;
        int b  = bn / NN;
        int n  = bn - b * NN;
        int eid = entity_ids[bn];
        s_nid[i] = adj_entity[eid * KK + k];
        int nk = n * KK + k;
        float a = __fdividef(g_exp[nk * BB + b], g_den[nk]);
        s_att2[i] = pack2(a, a);
    }
    __syncthreads();

    int p    = t & 63;      // d-pair index: d0 = 2p
    int half = t >> 6;      // 0/1 -> rows half*8 .. half*8+7
    int d0   = 2 * p;

    // ---- Phase B: 4 iterations x 2 interleaved rows ----
    #pragma unroll 1
    for (int mp = 0; mp < 4; mp++) {
        int rA = half * 8 + 2 * mp;
        int rB = rA + 1;

        ull eeA = *(const ull*)(ent_emb + (size_t)s_eid[rA] * DD + d0);
        ull eeB = *(const ull*)(ent_emb + (size_t)s_eid[rB] * DD + d0);

        ull vA[KK], vB[KK];
        #pragma unroll
        for (int k = 0; k < KK; k++)
            vA[k] = *(const ull*)(ent_emb + (size_t)s_nid[rA * KK + k] * DD + d0);
        #pragma unroll
        for (int k = 0; k < KK; k++)
            vB[k] = *(const ull*)(ent_emb + (size_t)s_nid[rB * KK + k] * DD + d0);

        ull accA = 0ull, accB = 0ull;
        #pragma unroll
        for (int k = 0; k < KK; k++) {
            accA = fma2(s_att2[rA * KK + k], vA[k], accA);
            accB = fma2(s_att2[rB * KK + k], vB[k], accB);
        }

        float lo, hi;
        unpack2(eeA, lo, hi);
        sT[(d0 + 0) * GPITCH + rA]      = lo;
        sT[(d0 + 1) * GPITCH + rA]      = hi;
        unpack2(accA, lo, hi);
        sT[(DD + d0 + 0) * GPITCH + rA] = lo;
        sT[(DD + d0 + 1) * GPITCH + rA] = hi;
        unpack2(eeB, lo, hi);
        sT[(d0 + 0) * GPITCH + rB]      = lo;
        sT[(d0 + 1) * GPITCH + rB]      = hi;
        unpack2(accB, lo, hi);
        sT[(DD + d0 + 0) * GPITCH + rB] = lo;
        sT[(DD + d0 + 1) * GPITCH + rB] = hi;
    }
    __syncthreads();

    // ---- Phase C ----
    int rg = half;

    ull acc[2][4];
    {
        ull i0 = pack2(b_conv[d0],     b_conv[d0]);
        ull i1 = pack2(b_conv[d0 + 1], b_conv[d0 + 1]);
        #pragma unroll
        for (int rp = 0; rp < 4; rp++) { acc[0][rp] = i0; acc[1][rp] = i1; }
    }

    const float* Wp = W_conv + d0;
    const float* sb = sT + rg * 8;

    float2 wb[8];
    #pragma unroll
    for (int i = 0; i < 8; i++)
        wb[i] = *(const float2*)(Wp + i * DD);

    #pragma unroll 1
    for (int jt = 0; jt < 2 * DD; jt += 8) {
        float2 wc[8];
        #pragma unroll
        for (int i = 0; i < 8; i++) wc[i] = wb[i];

        int jn = (jt + 8) & (2 * DD - 1);
        #pragma unroll
        for (int i = 0; i < 8; i++)
            wb[i] = *(const float2*)(Wp + (jn + i) * DD);

        #pragma unroll
        for (int i = 0; i < 8; i++) {
            int j = jt + i;
            ull w0 = pack2(wc[i].x, wc[i].x);
            ull w1 = pack2(wc[i].y, wc[i].y);
            ulonglong2 pa = *(const ulonglong2*)(sb + j * GPITCH);       // rows 0-3
            ulonglong2 pb = *(const ulonglong2*)(sb + j * GPITCH + 4);   // rows 4-7
            acc[0][0] = fma2(pa.x, w0, acc[0][0]);
            acc[1][0] = fma2(pa.x, w1, acc[1][0]);
            acc[0][1] = fma2(pa.y, w0, acc[0][1]);
            acc[1][1] = fma2(pa.y, w1, acc[1][1]);
            acc[0][2] = fma2(pb.x, w0, acc[0][2]);
            acc[1][2] = fma2(pb.x, w1, acc[1][2]);
            acc[0][3] = fma2(pb.y, w0, acc[0][3]);
            acc[1][3] = fma2(pb.y, w1, acc[1][3]);
        }
    }

    #pragma unroll
    for (int rp = 0; rp < 4; rp++) {
        float lo0, hi0, lo1, hi1;
        unpack2(acc[0][rp], lo0, hi0);
        unpack2(acc[1][rp], lo1, hi1);
        int r0 = bn0 + rg * 8 + rp * 2;
        float2 o0 = make_float2(fmaxf(lo0, 0.0f), fmaxf(lo1, 0.0f));
        float2 o1 = make_float2(fmaxf(hi0, 0.0f), fmaxf(hi1, 0.0f));
        *(float2*)(out + (size_t)r0 * DD + d0)       = o0;
        *(float2*)(out + (size_t)(r0 + 1) * DD + d0) = o1;
    }
}

// ---------------------------------------------------------------------------
extern "C" void kernel_launch(void* const* d_in, const int* in_sizes, int n_in,
                              void* d_out, int out_size)
{
    const int*   entity_ids = (const int*)  d_in[0];
    const int*   adj_entity = (const int*)  d_in[1];
    const int*   adj_rel    = (const int*)  d_in[2];
    const float* ent_emb    = (const float*)d_in[3];
    const float* rel_emb    = (const float*)d_in[4];
    const float* W_att      = (const float*)d_in[5];
    const float* b_att      = (const float*)d_in[6];
    const float* W_conv     = (const float*)d_in[7];
    const float* b_conv     = (const float*)d_in[8];
    float* out = (float*)d_out;

    k_pre<<<(PRE_W + 7) / 8, 256>>>(entity_ids, ent_emb, rel_emb, W_att);

    k_logits<<<TOT / 4 / 8, 256>>>(entity_ids, adj_entity, adj_rel,
                                   ent_emb, W_att, b_att);

    k_gg<<<BN / GROWS, 128>>>(entity_ids, adj_entity, ent_emb,
                              W_conv, b_conv, out);
}